// round 1
// baseline (speedup 1.0000x reference)
#include <cuda_runtime.h>
#include <math.h>

// Problem constants (fixed by the dataset): B=8, H=1024, E=512, V=32000, T=100
#define VOCAB 32000
#define BATCH 8
#define HDIM  1024
#define EDIM  512
#define XV    (HDIM + EDIM)        // 1536  (x_v = [output, input_step])
#define XK    (2 * HDIM + EDIM)    // 2560  (x_k = [output, input_step, context])

// ---------------------------------------------------------------------------
// Kernel 1: e_v path for ALL words.
// energy_default[b][w] = tanh(x_v[b] . W_V[w] + b_V[w]); store u = exp(energy).
// Warp handles 4 consecutive words; x_v for all 8 batches lives in smem.
// W_V is streamed exactly once (196.6 MB) -> HBM-bound.
// ---------------------------------------------------------------------------
__global__ void __launch_bounds__(256) ev_main_kernel(
    const float* __restrict__ gru,   // [B, H]   (output)
    const float* __restrict__ emb,   // [B, E]   (input_step)
    const float* __restrict__ W_V,   // [V, XV]
    const float* __restrict__ b_V,   // [V]
    float* __restrict__ out)         // [B, V]
{
    __shared__ __align__(16) float xs[BATCH][XV];   // 48 KB

    int tid = threadIdx.x;
    // Cooperative load of x_v into smem (3072 float4, 12 per thread).
    for (int i = tid; i < BATCH * XV / 4; i += 256) {
        int idx = i * 4;
        int b = idx / XV;
        int c = idx - b * XV;
        float4 v;
        if (c < HDIM) v = *(const float4*)&gru[b * HDIM + c];
        else          v = *(const float4*)&emb[b * EDIM + (c - HDIM)];
        *(float4*)&xs[b][c] = v;
    }
    __syncthreads();

    int warp = tid >> 5;
    int lane = tid & 31;
    int w0 = (blockIdx.x * 8 + warp) * 4;          // 4 words per warp
    if (w0 >= VOCAB) return;

    float acc[4][8];
#pragma unroll
    for (int wi = 0; wi < 4; wi++)
#pragma unroll
        for (int b = 0; b < 8; b++) acc[wi][b] = 0.0f;

    const float* Wr = W_V + (size_t)w0 * XV;

#pragma unroll 2
    for (int it = 0; it < XV / 128; ++it) {        // 12 iterations
        int c = it * 128 + lane * 4;
        float4 xv[8];
#pragma unroll
        for (int b = 0; b < 8; b++) xv[b] = *(const float4*)&xs[b][c];
#pragma unroll
        for (int wi = 0; wi < 4; wi++) {
            float4 wv = *(const float4*)&Wr[(size_t)wi * XV + c];
#pragma unroll
            for (int b = 0; b < 8; b++) {
                acc[wi][b] += wv.x * xv[b].x + wv.y * xv[b].y
                            + wv.z * xv[b].z + wv.w * xv[b].w;
            }
        }
    }

    // Warp-reduce all 32 partial dot products.
#pragma unroll
    for (int wi = 0; wi < 4; wi++)
#pragma unroll
        for (int b = 0; b < 8; b++)
#pragma unroll
            for (int o = 16; o > 0; o >>= 1)
                acc[wi][b] += __shfl_xor_sync(0xffffffffu, acc[wi][b], o);

    // Lane (wi = lane/8, b = lane%8) writes its (word, batch) result.
    int wi = lane >> 3;
    int b  = lane & 7;
    float e = acc[wi][b] + b_V[w0 + wi];
    out[(size_t)b * VOCAB + (w0 + wi)] = expf(tanhf(e));
}

// ---------------------------------------------------------------------------
// Kernel 2: fixup for words present in the topic list (k > 0 => v = 0).
// One warp per (b, t). Count recomputed on the fly; duplicates write the
// same value (benign). Touches <= 800 W_K rows (~8 MB) instead of 327 MB.
// ---------------------------------------------------------------------------
__global__ void __launch_bounds__(256) ek_fixup_kernel(
    const float* __restrict__ gru,   // [B, H]
    const float* __restrict__ emb,   // [B, E]
    const float* __restrict__ ctx,   // [B, H]
    const int*   __restrict__ topic, // [B, T]
    int T,
    const float* __restrict__ W_K,   // [V, XK]
    const float* __restrict__ b_K,   // [V]
    float* __restrict__ out)         // [B, V]
{
    int gw   = (int)((blockIdx.x * blockDim.x + threadIdx.x) >> 5);
    int lane = threadIdx.x & 31;
    if (gw >= BATCH * T) return;
    int b = gw / T;
    int t = gw - b * T;

    int w = topic[b * T + t];
    if (w == 0) return;                            // pad index contributes nothing

    // count occurrences of w in row b
    int cnt = 0;
    for (int tt = lane; tt < T; tt += 32)
        cnt += (topic[b * T + tt] == w) ? 1 : 0;
#pragma unroll
    for (int o = 16; o > 0; o >>= 1)
        cnt += __shfl_xor_sync(0xffffffffu, cnt, o);

    // e_k = x_k[b] . W_K[w] + b_K[w]   (2560-wide, warp-collective)
    const float* Wr = W_K + (size_t)w * XK;
    float s = 0.0f;
    for (int c = lane * 4; c < XK; c += 128) {     // 20 iterations
        float4 wv = *(const float4*)&Wr[c];
        float4 xv;
        if (c < HDIM)      xv = *(const float4*)&gru[b * HDIM + c];
        else if (c < XV)   xv = *(const float4*)&emb[b * EDIM + (c - HDIM)];
        else               xv = *(const float4*)&ctx[b * HDIM + (c - XV)];
        s += wv.x * xv.x + wv.y * xv.y + wv.z * xv.z + wv.w * xv.w;
    }
#pragma unroll
    for (int o = 16; o > 0; o >>= 1)
        s += __shfl_xor_sync(0xffffffffu, s, o);

    if (lane == 0) {
        float e = (float)cnt * (s + b_K[w]);
        out[(size_t)b * VOCAB + w] = expf(tanhf(e));
    }
}

// ---------------------------------------------------------------------------
// Kernel 3: softmax normalization. out already holds exp(energy) with
// energy in [-1, 1], so no max-subtraction needed; just sum + scale.
// ---------------------------------------------------------------------------
__global__ void __launch_bounds__(1024) softmax_norm_kernel(float* __restrict__ out)
{
    int b = blockIdx.x;
    float* row = out + (size_t)b * VOCAB;

    float s = 0.0f;
    for (int i = threadIdx.x * 4; i < VOCAB; i += 1024 * 4) {
        float4 v = *(const float4*)&row[i];
        s += (v.x + v.y) + (v.z + v.w);
    }

    __shared__ float red[32];
    int lane = threadIdx.x & 31;
    int wid  = threadIdx.x >> 5;
#pragma unroll
    for (int o = 16; o > 0; o >>= 1)
        s += __shfl_xor_sync(0xffffffffu, s, o);
    if (lane == 0) red[wid] = s;
    __syncthreads();
    if (wid == 0) {
        s = red[lane];
#pragma unroll
        for (int o = 16; o > 0; o >>= 1)
            s += __shfl_xor_sync(0xffffffffu, s, o);
        if (lane == 0) red[0] = s;
    }
    __syncthreads();

    float inv = 1.0f / red[0];
    for (int i = threadIdx.x * 4; i < VOCAB; i += 1024 * 4) {
        float4 v = *(const float4*)&row[i];
        v.x *= inv; v.y *= inv; v.z *= inv; v.w *= inv;
        *(float4*)&row[i] = v;
    }
}

// ---------------------------------------------------------------------------
// Launcher. Input order (metadata): output, input_step, context,
// topic_indexs, [topic_length?], W_V, b_V, W_K, b_K.
// Identify W_V/W_K by element count so the optional scalar can't shift us.
// ---------------------------------------------------------------------------
extern "C" void kernel_launch(void* const* d_in, const int* in_sizes, int n_in,
                              void* d_out, int out_size)
{
    const float* gru   = (const float*)d_in[0];
    const float* emb   = (const float*)d_in[1];
    const float* ctx   = (const float*)d_in[2];
    const int*   topic = (const int*)d_in[3];
    int T = in_sizes[3] / BATCH;

    const float* W_V = nullptr; const float* b_V = nullptr;
    const float* W_K = nullptr; const float* b_K = nullptr;
    for (int i = 4; i < n_in; ++i) {
        long sz = (long)in_sizes[i];
        if (sz == (long)VOCAB * XV && i + 1 < n_in) {
            W_V = (const float*)d_in[i];
            b_V = (const float*)d_in[i + 1];
        } else if (sz == (long)VOCAB * XK && i + 1 < n_in) {
            W_K = (const float*)d_in[i];
            b_K = (const float*)d_in[i + 1];
        }
    }

    float* out = (float*)d_out;

    // 1) default path: all 256K entries
    ev_main_kernel<<<VOCAB / 32, 256>>>(gru, emb, W_V, b_V, out);

    // 2) fixup topic-word entries (one warp per (b,t))
    int nwarps  = BATCH * T;
    int nblocks = (nwarps * 32 + 255) / 256;
    ek_fixup_kernel<<<nblocks, 256>>>(gru, emb, ctx, topic, T, W_K, b_K, out);

    // 3) normalize
    softmax_norm_kernel<<<BATCH, 1024>>>(out);
}